// round 6
// baseline (speedup 1.0000x reference)
#include <cuda_runtime.h>
#include <math.h>

#define N_VARS 64
#define NV1    65      // N = n_vars + 1
#define M_CL   256
#define KD     12
#define CST    72      // padded C row stride in floats (cols 65..71 zero)
#define NPAIR  33      // f32x2 pairs covering n = 0..65 (slot 65 is zero pad)

// Gram matrix C = Sw^T Sw with ZEROED DIAGONAL, padded rows
__device__ __align__(16) float g_C[NV1 * CST];

typedef unsigned long long u64;

// ---- packed f32x2 primitives (pure PTX, operands stay in u64 pairs) --------
__device__ __forceinline__ u64 ffma2u(u64 a, u64 b, u64 c)
{
    u64 d;
    asm("fma.rn.f32x2 %0, %1, %2, %3;" : "=l"(d) : "l"(a), "l"(b), "l"(c));
    return d;
}
__device__ __forceinline__ u64 fadd2u(u64 a, u64 b)
{
    u64 d;
    asm("add.rn.f32x2 %0, %1, %2;" : "=l"(d) : "l"(a), "l"(b));
    return d;
}
__device__ __forceinline__ u64 pack2(float x, float y)
{
    u64 d;
    asm("mov.b64 %0, {%1, %2};" : "=l"(d) : "f"(x), "f"(y));
    return d;
}
__device__ __forceinline__ void unpack2(u64 p, float& x, float& y)
{
    asm("mov.b64 {%0, %1}, %2;" : "=f"(x), "=f"(y) : "l"(p));
}

// full 65-wide packed dot of C row with per-lane V (pairs 0..32)
__device__ __forceinline__ float dot_full(const float* __restrict__ rowF,
                                          const u64* __restrict__ Vp)
{
    const ulonglong2* cr = (const ulonglong2*)rowF;    // rows are 16B-aligned (CST=72)
    u64 a0 = 0ull, a1 = 0ull, a2 = 0ull, a3 = 0ull;
#pragma unroll
    for (int c = 0; c < 16; ++c) {                     // pairs 0..31
        const ulonglong2 cv = cr[c];
        if (c & 1) {
            a2 = ffma2u(cv.x, Vp[2 * c + 0], a2);
            a3 = ffma2u(cv.y, Vp[2 * c + 1], a3);
        } else {
            a0 = ffma2u(cv.x, Vp[2 * c + 0], a0);
            a1 = ffma2u(cv.y, Vp[2 * c + 1], a1);
        }
    }
    const u64 c32 = *(const u64*)(rowF + 64);          // pair 32 (floats 64,65)
    a0 = ffma2u(c32, Vp[32], a0);
    const u64 tt = fadd2u(fadd2u(a0, a2), fadd2u(a1, a3));
    float x, y;
    unpack2(tt, x, y);
    return x + y;
}

// ---------------------------------------------------------------------------
// Kernel 1: C[i][j] = sum_m (S[m,i]*w[m]) * (S[m,j]*w[m]);  C[i][i] = 0
// ---------------------------------------------------------------------------
__global__ void gram_kernel(const float* __restrict__ S, const float* __restrict__ w)
{
    const int i = blockIdx.x;    // 0..64
    const int j = threadIdx.x;   // 0..71
    float acc = 0.f;
    if (j < NV1) {
#pragma unroll 16
        for (int m = 0; m < M_CL; ++m) {
            const float wm = __ldg(&w[m]);
            acc = fmaf(__ldg(&S[m * NV1 + i]) * wm, __ldg(&S[m * NV1 + j]) * wm, acc);
        }
    }
    g_C[i * CST + j] = (j < NV1 && j != i) ? acc : 0.f;
}

// ---------------------------------------------------------------------------
// Kernel 2: pipelined coordinate descent, TWO batch elements per warp.
// Lane = h*16 + k: group h handles batch 2*warp_b + h; k in [0,12) active.
// Each lane holds FULL V[k][0..64] as 33 packed f32x2 registers.
// Recurrence: g_i = P_i + C[i,i-1]*v_{i-1}  =>  g = fma(t, inv, P)
// Norm reductions stay inside each 16-lane group (xor widths <= 15).
// ---------------------------------------------------------------------------
__global__ void __launch_bounds__(128, 1)
mix_kernel(const float* __restrict__ z, const float* __restrict__ r,
           const int* __restrict__ miter_p, float* __restrict__ out, int B)
{
    __shared__ __align__(16) float Csh[NV1 * CST];   // 18,720 B
    {
        const float4* src = (const float4*)g_C;
        float4* dst = (float4*)Csh;
#pragma unroll 4
        for (int t = threadIdx.x; t < (NV1 * CST) / 4; t += 128) dst[t] = src[t];
    }
    __syncthreads();

    const int lane = threadIdx.x & 31;
    const int warp = threadIdx.x >> 5;
    const int k = lane & 15;                 // component index (0..11 active)
    const int h = lane >> 4;                 // batch sub-slot within warp
    const int b = (blockIdx.x * 4 + warp) * 2 + h;
    if (b >= B) return;

    const unsigned FULL = 0xffffffffu;
    const float PI = 3.14159265358979323846f;
    const int miter = miter_p ? *miter_p : 12;

    u64 Vp[NPAIR];                           // packed V: pair jp = (n=2jp, 2jp+1)

    // ---- init: V[0]=e0; V[n] = -cos(pi z)e0 + sin(pi z) r_perp_hat ----
#pragma unroll
    for (int jp = 0; jp < NPAIR; ++jp) {
        float vv[2];
#pragma unroll
        for (int q = 0; q < 2; ++q) {
            const int n  = 2 * jp + q;
            const int nc = (n < 1) ? 1 : ((n > 64) ? 64 : n);
            const float zv = z[b * N_VARS + nc - 1];
            const float rv = r[(b * N_VARS + nc - 1) * KD + ((k < KD) ? k : 0)];
            const float rp = (k >= 1 && k < KD) ? rv : 0.f;
            float s = rp * rp;                       // ||r_perp||^2 over k (16-group)
            s += __shfl_xor_sync(FULL, s, 8);
            s += __shfl_xor_sync(FULL, s, 4);
            s += __shfl_xor_sync(FULL, s, 2);
            s += __shfl_xor_sync(FULL, s, 1);
            const float inv0 = (s > 1e-16f) ? rsqrtf(s) : 1e8f;
            float sn, cs;
            __sincosf(PI * zv, &sn, &cs);
            float v = sn * (rp * inv0);
            if (k == 0) v -= cs;
            const bool active = (n >= 1 && n <= 64);
            vv[q] = active ? v : ((n == 0) ? ((k == 0) ? 1.f : 0.f) : 0.f);
        }
        Vp[jp] = pack2(vv[0], vv[1]);
    }

    // ---- pipelined sweeps ----
    float P, t = 0.f, inv = 0.f;

    // prologue: P = full dot of row 1 (no pending coordinate)
    P = dot_full(Csh + 1 * CST, Vp);

    for (int it = 0; it < miter; ++it) {
#pragma unroll
        for (int i = 1; i < NV1; ++i) {
            const int jp = i >> 1;                // packed slot of coord i
            const int inext = (i < 64) ? i + 1 : 1;

            // -------- critical chain: g, ||g||^2 (within 16-lane group) ----
            const float g = fmaf(t, inv, P);

            const float c1 = __shfl_xor_sync(FULL, g, 4);
            const float c2 = __shfl_xor_sync(FULL, g, 8);
            const float c3 = __shfl_xor_sync(FULL, g, 12);
            float s4 = g * g;
            s4 = fmaf(c1, c1, s4);
            s4 = fmaf(c2, c2, s4);
            s4 = fmaf(c3, c3, s4);
            const float d1 = __shfl_xor_sync(FULL, s4, 1);
            const float d2 = __shfl_xor_sync(FULL, s4, 2);
            const float d3 = __shfl_xor_sync(FULL, s4, 3);
            float s = (s4 + d1) + (d2 + d3);
            s = fmaxf(s, 1e-16f);

            // -------- off-chain: next-row packed dot (per-lane, full) ------
            const float cni = Csh[inext * CST + i];   // C[inext][i]
            t = -cni * g;                             // pending-term coeff

            float acc = dot_full(Csh + inext * CST, Vp);

            float vx, vy;
            unpack2(Vp[jp], vx, vy);
            const float vold = (i & 1) ? vy : vx;
            acc = fmaf(-cni, vold, acc);              // remove OLD V[i] term
            P = acc;

            // -------- finish chain, commit v_i (lane-local slot) -----------
            inv = rsqrtf(s);
            const float v = -g * inv;
            if (i & 1) Vp[jp] = pack2(vx, v);
            else       Vp[jp] = pack2(v, vy);
        }
    }

    // ---- output: out[b][n-1] = acos(clip(-V[0][n])) / pi ----
    if (k == 0) {
#pragma unroll
        for (int jp = 0; jp < NPAIR; ++jp) {
            float vals[2];
            unpack2(Vp[jp], vals[0], vals[1]);
#pragma unroll
            for (int q = 0; q < 2; ++q) {
                const int n = 2 * jp + q;
                if (n >= 1 && n <= 64) {
                    float c = -vals[q];
                    c = fminf(fmaxf(c, -1.f + 1e-6f), 1.f - 1e-6f);
                    out[b * N_VARS + (n - 1)] = acosf(c) * (1.0f / PI);
                }
            }
        }
    }
}

// ---------------------------------------------------------------------------
extern "C" void kernel_launch(void* const* d_in, const int* in_sizes, int n_in,
                              void* d_out, int out_size)
{
    const float* z = (const float*)d_in[0];
    const float* S = (const float*)d_in[1];
    const float* w = (const float*)d_in[2];
    const float* r = (const float*)d_in[3];
    const int* mi  = (n_in > 4) ? (const int*)d_in[4] : nullptr;
    float* out = (float*)d_out;

    const int B = in_sizes[0] / N_VARS;

    gram_kernel<<<NV1, CST>>>(S, w);
    // 2 batches per warp, 4 warps per block -> 8 batches per block
    mix_kernel<<<(B + 7) / 8, 128>>>(z, r, mi, out, B);
}

// round 7
// speedup vs baseline: 5.7421x; 5.7421x over previous
#include <cuda_runtime.h>
#include <math.h>

#define N_VARS 64
#define NV1    65      // N = n_vars + 1
#define M_CL   256
#define KD     12
#define CST    72      // padded C row stride in floats (cols 65..71 zero)
#define HALF   36      // n-range width per lane-half
#define NP     18      // f32x2 pairs per half

// Gram matrix C = Sw^T Sw with ZEROED DIAGONAL, padded rows
__device__ __align__(16) float g_C[NV1 * CST];

typedef unsigned long long u64;

// ---- packed f32x2 primitives (pure PTX, operands stay in u64 pairs) --------
__device__ __forceinline__ u64 ffma2u(u64 a, u64 b, u64 c)
{
    u64 d;
    asm("fma.rn.f32x2 %0, %1, %2, %3;" : "=l"(d) : "l"(a), "l"(b), "l"(c));
    return d;
}
__device__ __forceinline__ u64 fadd2u(u64 a, u64 b)
{
    u64 d;
    asm("add.rn.f32x2 %0, %1, %2;" : "=l"(d) : "l"(a), "l"(b));
    return d;
}
__device__ __forceinline__ u64 pack2(float x, float y)
{
    u64 d;
    asm("mov.b64 %0, {%1, %2};" : "=l"(d) : "f"(x), "f"(y));
    return d;
}
__device__ __forceinline__ void unpack2(u64 p, float& x, float& y)
{
    asm("mov.b64 {%0, %1}, %2;" : "=f"(x), "=f"(y) : "l"(p));
}

// ---------------------------------------------------------------------------
// Kernel 1: C[i][j] = sum_m (S[m,i]*w[m]) * (S[m,j]*w[m]);  C[i][i] = 0
// ---------------------------------------------------------------------------
__global__ void gram_kernel(const float* __restrict__ S, const float* __restrict__ w)
{
    const int i = blockIdx.x;    // 0..64
    const int j = threadIdx.x;   // 0..71
    float acc = 0.f;
    if (j < NV1) {
#pragma unroll 16
        for (int m = 0; m < M_CL; ++m) {
            const float wm = __ldg(&w[m]);
            acc = fmaf(__ldg(&S[m * NV1 + i]) * wm, __ldg(&S[m * NV1 + j]) * wm, acc);
        }
    }
    g_C[i * CST + j] = (j < NV1 && j != i) ? acc : 0.f;
}

// ---------------------------------------------------------------------------
// Kernel 2: pipelined coordinate descent. ONE warp per CTA, one batch/warp.
// Lane = h*16 + k, k in [0,12) active, h in {0,1}.
// Lane (h,k) holds V[k][n] for n in [36h, 36h+36) as 18 packed f32x2 regs.
// Loop body order: (1) LDS next C row into regs, (2) shuffle-reduce norm,
// (3) packed dot with preloaded row (overlaps shfl latency), (4) rsqrt+commit.
// ---------------------------------------------------------------------------
__global__ void __launch_bounds__(32, 1)
mix_kernel(const float* __restrict__ z, const float* __restrict__ r,
           const int* __restrict__ miter_p, float* __restrict__ out, int B)
{
    __shared__ __align__(16) float Csh[NV1 * CST];   // 18,720 B
    {
        const float4* src = (const float4*)g_C;
        float4* dst = (float4*)Csh;
#pragma unroll 8
        for (int t = threadIdx.x; t < (NV1 * CST) / 4; t += 32) dst[t] = src[t];
    }
    __syncthreads();

    const int lane = threadIdx.x & 31;
    const int b    = blockIdx.x;
    if (b >= B) return;

    const int k = lane & 15;      // component index (0..11 active)
    const int h = lane >> 4;      // which n-half
    const unsigned FULL = 0xffffffffu;
    const float PI = 3.14159265358979323846f;
    const int miter = miter_p ? *miter_p : 12;

    u64 Vp[NP];                   // packed V: pair jp = (n=36h+2jp, n+1)

    // ---- init: V[0]=e0; V[n] = -cos(pi z)e0 + sin(pi z) r_perp_hat ----
#pragma unroll
    for (int jp = 0; jp < NP; ++jp) {
        float vv[2];
#pragma unroll
        for (int q = 0; q < 2; ++q) {
            const int j  = 2 * jp + q;
            const int n  = HALF * h + j;
            const int nc = (n < 1) ? 1 : ((n > 64) ? 64 : n);
            const float zv = z[b * N_VARS + nc - 1];
            const float rv = r[(b * N_VARS + nc - 1) * KD + ((k < KD) ? k : 0)];
            const float rp = (k >= 1 && k < KD) ? rv : 0.f;
            float s = rp * rp;
            s += __shfl_xor_sync(FULL, s, 8);
            s += __shfl_xor_sync(FULL, s, 4);
            s += __shfl_xor_sync(FULL, s, 2);
            s += __shfl_xor_sync(FULL, s, 1);
            const float inv0 = (s > 1e-16f) ? rsqrtf(s) : 1e8f;
            float sn, cs;
            __sincosf(PI * zv, &sn, &cs);
            float v = sn * (rp * inv0);
            if (k == 0) v -= cs;
            const bool active = (n >= 1 && n <= 64);
            vv[q] = active ? v : ((n == 0) ? ((k == 0) ? 1.f : 0.f) : 0.f);
        }
        Vp[jp] = pack2(vv[0], vv[1]);
    }

    // ---- pipelined sweeps ----
    float P, t = 0.f, inv = 0.f;

    // prologue: P = full dot of row 1 (no pending coordinate)
    {
        const ulonglong2* cr = (const ulonglong2*)(Csh + 1 * CST + HALF * h);
        u64 a0 = 0ull, a1 = 0ull, a2 = 0ull, a3 = 0ull;
#pragma unroll
        for (int c = 0; c < 9; ++c) {
            const ulonglong2 cv = cr[c];
            if (c & 1) { a2 = ffma2u(cv.x, Vp[2*c+0], a2); a3 = ffma2u(cv.y, Vp[2*c+1], a3); }
            else       { a0 = ffma2u(cv.x, Vp[2*c+0], a0); a1 = ffma2u(cv.y, Vp[2*c+1], a1); }
        }
        const u64 tt = fadd2u(fadd2u(a0, a2), fadd2u(a1, a3));
        float x, y; unpack2(tt, x, y);
        const float acc = x + y;
        P = acc + __shfl_xor_sync(FULL, acc, 16);
    }

    for (int it = 0; it < miter; ++it) {
#pragma unroll
        for (int i = 1; i < NV1; ++i) {
            const int hi = (i < HALF) ? 0 : 1;    // owning half of coord i
            const int ji = i - HALF * hi;         // element slot in owner
            const int jp = ji >> 1;               // packed slot (compile-time)
            const int inext = (i < 64) ? i + 1 : 1;

            // ---- (1) issue next-row LDS FIRST (latency hides under shfl) --
            const float cni = Csh[inext * CST + i];          // C[inext][i]
            const ulonglong2* cr = (const ulonglong2*)(Csh + inext * CST + HALF * h);
            ulonglong2 row[5];
            row[0] = cr[0]; row[1] = cr[1]; row[2] = cr[2];
            row[3] = cr[3]; row[4] = cr[4];
            ulonglong2 row5 = cr[5], row6 = cr[6], row7 = cr[7], row8 = cr[8];

            // ---- (2) critical chain: g, ||g||^2 ---------------------------
            const float g = fmaf(t, inv, P);

            const float c1 = __shfl_xor_sync(FULL, g, 4);
            const float c2 = __shfl_xor_sync(FULL, g, 8);
            const float c3 = __shfl_xor_sync(FULL, g, 12);
            float s4 = g * g;
            s4 = fmaf(c1, c1, s4);
            s4 = fmaf(c2, c2, s4);
            s4 = fmaf(c3, c3, s4);
            const float d1 = __shfl_xor_sync(FULL, s4, 1);
            const float d2 = __shfl_xor_sync(FULL, s4, 2);
            const float d3 = __shfl_xor_sync(FULL, s4, 3);
            float s = (s4 + d1) + (d2 + d3);
            s = fmaxf(s, 1e-16f);

            // ---- (3) off-chain: packed dot with preloaded row -------------
            t = -cni * g;                                    // pending coeff

            u64 a0 = 0ull, a1 = 0ull, a2 = 0ull, a3 = 0ull;
#pragma unroll
            for (int c = 0; c < 5; ++c) {
                if (c & 1) { a2 = ffma2u(row[c].x, Vp[2*c+0], a2); a3 = ffma2u(row[c].y, Vp[2*c+1], a3); }
                else       { a0 = ffma2u(row[c].x, Vp[2*c+0], a0); a1 = ffma2u(row[c].y, Vp[2*c+1], a1); }
            }
            a2 = ffma2u(row5.x, Vp[10], a2); a3 = ffma2u(row5.y, Vp[11], a3);
            a0 = ffma2u(row6.x, Vp[12], a0); a1 = ffma2u(row6.y, Vp[13], a1);
            a2 = ffma2u(row7.x, Vp[14], a2); a3 = ffma2u(row7.y, Vp[15], a3);
            a0 = ffma2u(row8.x, Vp[16], a0); a1 = ffma2u(row8.y, Vp[17], a1);
            const u64 tt = fadd2u(fadd2u(a0, a2), fadd2u(a1, a3));
            float x, y; unpack2(tt, x, y);
            float acc = x + y;

            float vx, vy;
            if (h == hi) {
                unpack2(Vp[jp], vx, vy);
                const float vold = (ji & 1) ? vy : vx;
                acc = fmaf(-cni, vold, acc);                 // remove OLD V[i]
            }
            P = acc + __shfl_xor_sync(FULL, acc, 16);

            // ---- (4) finish chain, commit v_i ------------------------------
            inv = rsqrtf(s);
            const float v = -g * inv;
            if (h == hi) {
                if (ji & 1) Vp[jp] = pack2(vx, v);
                else        Vp[jp] = pack2(v, vy);
            }
        }
    }

    // ---- output: out[b][n-1] = acos(clip(-V[0][n])) / pi ----
    if (k == 0) {
#pragma unroll
        for (int jp = 0; jp < NP; ++jp) {
            float vals[2];
            unpack2(Vp[jp], vals[0], vals[1]);
#pragma unroll
            for (int q = 0; q < 2; ++q) {
                const int n = HALF * h + 2 * jp + q;
                if (n >= 1 && n <= 64) {
                    float c = -vals[q];
                    c = fminf(fmaxf(c, -1.f + 1e-6f), 1.f - 1e-6f);
                    out[b * N_VARS + (n - 1)] = acosf(c) * (1.0f / PI);
                }
            }
        }
    }
}

// ---------------------------------------------------------------------------
extern "C" void kernel_launch(void* const* d_in, const int* in_sizes, int n_in,
                              void* d_out, int out_size)
{
    const float* z = (const float*)d_in[0];
    const float* S = (const float*)d_in[1];
    const float* w = (const float*)d_in[2];
    const float* r = (const float*)d_in[3];
    const int* mi  = (n_in > 4) ? (const int*)d_in[4] : nullptr;
    float* out = (float*)d_out;

    const int B = in_sizes[0] / N_VARS;

    gram_kernel<<<NV1, CST>>>(S, w);
    // one 32-thread CTA per batch element: even ~7 warps/SM, no 2x-loaded SMs
    mix_kernel<<<B, 32>>>(z, r, mi, out, B);
}

// round 8
// speedup vs baseline: 6.0171x; 1.0479x over previous
#include <cuda_runtime.h>
#include <math.h>

#define N_VARS 64
#define NV1    65      // N = n_vars + 1
#define M_CL   256
#define KD     12
#define CST    72      // padded C row stride in floats (cols 65..71 zero)
#define HALF   36      // n-range width per lane-half
#define NP     18      // f32x2 pairs per half

// Gram matrix C = Sw^T Sw with ZEROED DIAGONAL, padded rows
__device__ __align__(16) float g_C[NV1 * CST];

typedef unsigned long long u64;

// ---- packed f32x2 primitives (pure PTX, operands stay in u64 pairs) --------
__device__ __forceinline__ u64 ffma2u(u64 a, u64 b, u64 c)
{
    u64 d;
    asm("fma.rn.f32x2 %0, %1, %2, %3;" : "=l"(d) : "l"(a), "l"(b), "l"(c));
    return d;
}
__device__ __forceinline__ u64 fadd2u(u64 a, u64 b)
{
    u64 d;
    asm("add.rn.f32x2 %0, %1, %2;" : "=l"(d) : "l"(a), "l"(b));
    return d;
}
__device__ __forceinline__ u64 pack2(float x, float y)
{
    u64 d;
    asm("mov.b64 %0, {%1, %2};" : "=l"(d) : "f"(x), "f"(y));
    return d;
}
__device__ __forceinline__ void unpack2(u64 p, float& x, float& y)
{
    asm("mov.b64 {%0, %1}, %2;" : "=f"(x), "=f"(y) : "l"(p));
}

// packed dot of one 36-wide C-row half with packed V
__device__ __forceinline__ float dot_half(const float* __restrict__ rowF,
                                          const u64* __restrict__ Vp)
{
    const ulonglong2* cr = (const ulonglong2*)rowF;    // 16B-aligned (CST=72, HALF=36)
    u64 a0 = 0ull, a1 = 0ull, a2 = 0ull, a3 = 0ull;
#pragma unroll
    for (int c = 0; c < 9; ++c) {
        const ulonglong2 cv = cr[c];
        if (c & 1) { a2 = ffma2u(cv.x, Vp[2*c+0], a2); a3 = ffma2u(cv.y, Vp[2*c+1], a3); }
        else       { a0 = ffma2u(cv.x, Vp[2*c+0], a0); a1 = ffma2u(cv.y, Vp[2*c+1], a1); }
    }
    const u64 tt = fadd2u(fadd2u(a0, a2), fadd2u(a1, a3));
    float x, y; unpack2(tt, x, y);
    return x + y;
}

// ---------------------------------------------------------------------------
// Kernel 1: C[i][j] = sum_m (S[m,i]*w[m]) * (S[m,j]*w[m]);  C[i][i] = 0
// ---------------------------------------------------------------------------
__global__ void gram_kernel(const float* __restrict__ S, const float* __restrict__ w)
{
    const int i = blockIdx.x;    // 0..64
    const int j = threadIdx.x;   // 0..71
    float acc = 0.f;
    if (j < NV1) {
#pragma unroll 16
        for (int m = 0; m < M_CL; ++m) {
            const float wm = __ldg(&w[m]);
            acc = fmaf(__ldg(&S[m * NV1 + i]) * wm, __ldg(&S[m * NV1 + j]) * wm, acc);
        }
    }
    g_C[i * CST + j] = (j < NV1 && j != i) ? acc : 0.f;
}

// ---------------------------------------------------------------------------
// Kernel 2: TWO-DEEP pipelined coordinate descent. One warp per batch.
// Lane = h*16 + k, k in [0,12) active, h in {0,1}.
// Lane (h,k) holds V[k][n] for n in [36h, 36h+36) as 18 packed f32x2 regs.
// At step i: consume P_i (prepared 2 steps ahead); compute D for row i+2
// with olds of coords i, i+1 removed; fold C[i+1,i-1]*v_{i-1} off-chain;
// the final C[i,i-1]*v_{i-1} term arrives via g = fma(t, inv, P).
// ---------------------------------------------------------------------------
__global__ void __launch_bounds__(128, 1)
mix_kernel(const float* __restrict__ z, const float* __restrict__ r,
           const int* __restrict__ miter_p, float* __restrict__ out, int B)
{
    __shared__ __align__(16) float Csh[NV1 * CST];   // 18,720 B
    {
        const float4* src = (const float4*)g_C;
        float4* dst = (float4*)Csh;
#pragma unroll 4
        for (int t = threadIdx.x; t < (NV1 * CST) / 4; t += 128) dst[t] = src[t];
    }
    __syncthreads();

    const int lane = threadIdx.x & 31;
    const int warp = threadIdx.x >> 5;
    const int b    = blockIdx.x * 4 + warp;
    if (b >= B) return;

    const int k = lane & 15;      // component index (0..11 active)
    const int h = lane >> 4;      // which n-half
    const unsigned FULL = 0xffffffffu;
    const float PI = 3.14159265358979323846f;
    const int miter = miter_p ? *miter_p : 12;

    u64 Vp[NP];                   // packed V: pair jp = (n=36h+2jp, n+1)

    // ---- init: V[0]=e0; V[n] = -cos(pi z)e0 + sin(pi z) r_perp_hat ----
#pragma unroll
    for (int jp = 0; jp < NP; ++jp) {
        float vv[2];
#pragma unroll
        for (int q = 0; q < 2; ++q) {
            const int j  = 2 * jp + q;
            const int n  = HALF * h + j;
            const int nc = (n < 1) ? 1 : ((n > 64) ? 64 : n);
            const float zv = z[b * N_VARS + nc - 1];
            const float rv = r[(b * N_VARS + nc - 1) * KD + ((k < KD) ? k : 0)];
            const float rp = (k >= 1 && k < KD) ? rv : 0.f;
            float s = rp * rp;
            s += __shfl_xor_sync(FULL, s, 8);
            s += __shfl_xor_sync(FULL, s, 4);
            s += __shfl_xor_sync(FULL, s, 2);
            s += __shfl_xor_sync(FULL, s, 1);
            const float inv0 = (s > 1e-16f) ? rsqrtf(s) : 1e8f;
            float sn, cs;
            __sincosf(PI * zv, &sn, &cs);
            float v = sn * (rp * inv0);
            if (k == 0) v -= cs;
            const bool active = (n >= 1 && n <= 64);
            vv[q] = active ? v : ((n == 0) ? ((k == 0) ? 1.f : 0.f) : 0.f);
        }
        Vp[jp] = pack2(vv[0], vv[1]);
    }

    // ---- prologue -----------------------------------------------------------
    // P for step 1: full dot of row 1 (V fresh, nothing pending)
    float P;
    {
        const float acc = dot_half(Csh + 1 * CST + HALF * h, Vp);
        P = acc + __shfl_xor_sync(FULL, acc, 16);
    }
    // Dc for row 2 with coord-1 old removed (coord 1 updates at step 1)
    float Dc;
    {
        float acc = dot_half(Csh + 2 * CST + HALF * h, Vp);
        if (h == 0) {                                   // slot 1 owner (pair 0, odd)
            float vx, vy; unpack2(Vp[0], vx, vy);
            acc = fmaf(-Csh[2 * CST + 1], vy, acc);
        }
        Dc = acc + __shfl_xor_sync(FULL, acc, 16);
    }
    float t = 0.f, inv = 0.f, v_prev = 0.f;
    float ca_prev = 0.f;                  // C[inext][iprev] for P correction
    float cb_prev = Csh[2 * CST + 1];     // C[inext][i] for t coeff

    // ---- two-deep pipelined sweeps -----------------------------------------
    for (int it = 0; it < miter; ++it) {
#pragma unroll
        for (int i = 1; i < NV1; ++i) {
            const int inext  = (i < 64) ? i + 1 : 1;
            const int innext = (i <= 62) ? i + 2 : i - 62;   // 63->1, 64->2

            const int hi_i = (i < HALF) ? 0 : 1;             // owner of slot i
            const int ji_i = i - HALF * hi_i;
            const int jp_i = ji_i >> 1;
            const int hi_x = (inext < HALF) ? 0 : 1;         // owner of slot inext
            const int ji_x = inext - HALF * hi_x;
            const int jp_x = ji_x >> 1;

            // scalar loads for this step (consumed next step as *_prev)
            const float ca = Csh[innext * CST + i];          // C[i+2][i]
            const float cb = Csh[innext * CST + inext];      // C[i+2][i+1]

            // -------- critical chain: g, ||g||^2 --------
            const float g = fmaf(t, inv, P);

            const float c1 = __shfl_xor_sync(FULL, g, 4);
            const float c2 = __shfl_xor_sync(FULL, g, 8);
            const float c3 = __shfl_xor_sync(FULL, g, 12);
            float s4 = g * g;
            s4 = fmaf(c1, c1, s4);
            s4 = fmaf(c2, c2, s4);
            s4 = fmaf(c3, c3, s4);
            const float d1 = __shfl_xor_sync(FULL, s4, 1);
            const float d2 = __shfl_xor_sync(FULL, s4, 2);
            const float d3 = __shfl_xor_sync(FULL, s4, 3);
            float s = (s4 + d1) + (d2 + d3);
            s = fmaxf(s, 1e-16f);

            // -------- off-chain: finish next step's P; next t ---------------
            const float Pn = fmaf(ca_prev, v_prev, Dc);  // + C[i+1][i-1]*v_{i-1}
            const float tn = -cb_prev * g;               // -C[i+1][i]*g_i

            // -------- off-chain: dot of row innext, olds removed ------------
            float acc = dot_half(Csh + innext * CST + HALF * h, Vp);
            float vx_i, vy_i;
            if (h == hi_i) {
                unpack2(Vp[jp_i], vx_i, vy_i);
                const float vold = (ji_i & 1) ? vy_i : vx_i;
                acc = fmaf(-ca, vold, acc);              // remove old coord i
            }
            if (h == hi_x) {
                float vx2, vy2; unpack2(Vp[jp_x], vx2, vy2);
                const float vold2 = (ji_x & 1) ? vy2 : vx2;
                acc = fmaf(-cb, vold2, acc);             // remove old coord i+1
            }
            const float Dn = acc + __shfl_xor_sync(FULL, acc, 16);

            // -------- finish chain, commit v_i -------------------------------
            inv = rsqrtf(s);
            const float v = -g * inv;
            if (h == hi_i) {
                if (ji_i & 1) Vp[jp_i] = pack2(vx_i, v);
                else          Vp[jp_i] = pack2(v, vy_i);
            }

            // rotate pipeline state
            P = Pn; t = tn; Dc = Dn; v_prev = v;
            ca_prev = ca; cb_prev = cb;
        }
    }

    // ---- output: out[b][n-1] = acos(clip(-V[0][n])) / pi ----
    if (k == 0) {
#pragma unroll
        for (int jp = 0; jp < NP; ++jp) {
            float vals[2];
            unpack2(Vp[jp], vals[0], vals[1]);
#pragma unroll
            for (int q = 0; q < 2; ++q) {
                const int n = HALF * h + 2 * jp + q;
                if (n >= 1 && n <= 64) {
                    float c = -vals[q];
                    c = fminf(fmaxf(c, -1.f + 1e-6f), 1.f - 1e-6f);
                    out[b * N_VARS + (n - 1)] = acosf(c) * (1.0f / PI);
                }
            }
        }
    }
}

// ---------------------------------------------------------------------------
extern "C" void kernel_launch(void* const* d_in, const int* in_sizes, int n_in,
                              void* d_out, int out_size)
{
    const float* z = (const float*)d_in[0];
    const float* S = (const float*)d_in[1];
    const float* w = (const float*)d_in[2];
    const float* r = (const float*)d_in[3];
    const int* mi  = (n_in > 4) ? (const int*)d_in[4] : nullptr;
    float* out = (float*)d_out;

    const int B = in_sizes[0] / N_VARS;

    gram_kernel<<<NV1, CST>>>(S, w);
    mix_kernel<<<(B + 3) / 4, 128>>>(z, r, mi, out, B);
}